// round 1
// baseline (speedup 1.0000x reference)
#include <cuda_runtime.h>
#include <math.h>

// Problem dims
#define B_    256
#define T_    128
#define NIN   700
#define H_    2048

// Scratch: U' = 0.5*(x@W_in + bias), layout [B*T, H]
__device__ float g_U[(size_t)B_ * T_ * H_];

// ----------------------------------------------------------------------------
// Kernel 1: input GEMM  C[M=B*T, N=H] = X[M, K=700] @ W[K, N], epilogue folds
// 0.5*(.+bias). Classic 128x128x8 SGEMM, 256 threads, 8x8 per thread.
// ----------------------------------------------------------------------------
__global__ void __launch_bounds__(256) k_input_gemm(
    const float* __restrict__ X, const float* __restrict__ W,
    const float* __restrict__ bias)
{
    constexpr int K = NIN, N = H_;
    constexpr int BM = 128, BN = 128, BK = 8, TM = 8, TN = 8;
    __shared__ float As[BK][BM];
    __shared__ float Bs[BK][BN];

    const int tid = threadIdx.x;
    const int bm = blockIdx.y, bn = blockIdx.x;

    const int aRow = tid >> 1;            // 0..127
    const int aCol = (tid & 1) << 2;      // 0 or 4
    const int bRow = tid >> 5;            // 0..7
    const int bCol = (tid & 31) << 2;     // 0..124

    const int tRow = (tid >> 4) << 3;     // 0..120
    const int tCol = (tid & 15) << 3;     // 0..120

    const float* Ab = X + (size_t)(bm * BM) * K;
    const float* Bb = W + bn * BN;

    float acc[TM][TN];
    #pragma unroll
    for (int i = 0; i < TM; i++)
        #pragma unroll
        for (int j = 0; j < TN; j++) acc[i][j] = 0.f;

    for (int k0 = 0; k0 < K; k0 += BK) {
        // load A tile (transposed into smem), guard ragged K=700
        #pragma unroll
        for (int i = 0; i < 4; i++) {
            int kk = k0 + aCol + i;
            As[aCol + i][aRow] = (kk < K) ? Ab[(size_t)aRow * K + kk] : 0.f;
        }
        // load B tile
        if (k0 + bRow < K) {
            float4 v = *(const float4*)(Bb + (size_t)(k0 + bRow) * N + bCol);
            Bs[bRow][bCol + 0] = v.x; Bs[bRow][bCol + 1] = v.y;
            Bs[bRow][bCol + 2] = v.z; Bs[bRow][bCol + 3] = v.w;
        } else {
            Bs[bRow][bCol + 0] = 0.f; Bs[bRow][bCol + 1] = 0.f;
            Bs[bRow][bCol + 2] = 0.f; Bs[bRow][bCol + 3] = 0.f;
        }
        __syncthreads();

        #pragma unroll
        for (int k = 0; k < BK; k++) {
            float aF[TM], bF[TN];
            #pragma unroll
            for (int i = 0; i < TM; i++) aF[i] = As[k][tRow + i];
            #pragma unroll
            for (int j = 0; j < TN; j++) bF[j] = Bs[k][tCol + j];
            #pragma unroll
            for (int i = 0; i < TM; i++)
                #pragma unroll
                for (int j = 0; j < TN; j++) acc[i][j] += aF[i] * bF[j];
        }
        __syncthreads();
    }

    const int m0 = bm * BM + tRow;
    const int n0 = bn * BN + tCol;
    #pragma unroll
    for (int i = 0; i < TM; i++) {
        size_t row = (size_t)(m0 + i) * N;
        #pragma unroll
        for (int j = 0; j < TN; j++)
            g_U[row + n0 + j] = 0.5f * (acc[i][j] + bias[n0 + j]);
    }
}

// ----------------------------------------------------------------------------
// Kernel 2: one recurrent frame.
//   r = spike_{t-1} @ A   (M=256 batch, K=H, N=H), fused epilogue:
//   y = tanh(0.5*r + U'), mem = mem_prev*0.5 - 0.5*(1-spike_prev) + y,
//   spike = mem > 0.5.
// Previous frame's mem/spike are read straight out of d_out (frame t-1 rows).
// 64x64x16 tile, 256 threads, 4x4 per thread. Grid 32x4 = 128 CTAs.
// ----------------------------------------------------------------------------
__global__ void __launch_bounds__(256) k_frame(
    const float* __restrict__ Arec, const float* __restrict__ mem_init,
    float* __restrict__ out_mems, float* __restrict__ out_spikes, int t)
{
    constexpr int N = H_;
    constexpr int BM = 64, BN = 64, BK = 16, TM = 4, TN = 4;
    __shared__ float Ss[BK][BM];
    __shared__ float Bs[BK][BN];

    const int tid = threadIdx.x;
    const int bm = blockIdx.y, bn = blockIdx.x;

    const int sRow = tid >> 2;            // 0..63 (batch within tile)
    const int sCol = (tid & 3) << 2;      // 0,4,8,12
    const int bRow = tid >> 4;            // 0..15
    const int bCol = (tid & 15) << 2;     // 0..60

    const int tRow = (tid >> 4) << 2;
    const int tCol = (tid & 15) << 2;

    float acc[TM][TN];
    #pragma unroll
    for (int i = 0; i < TM; i++)
        #pragma unroll
        for (int j = 0; j < TN; j++) acc[i][j] = 0.f;

    if (t > 0) {
        // spike rows for frame t-1: out_spikes[(b*T + t-1)*H + k]
        const size_t bstride = (size_t)T_ * N;
        const float* Sb = out_spikes + (size_t)(t - 1) * N
                        + (size_t)(bm * BM + sRow) * bstride;
        const float* Bb = Arec + bn * BN;

        for (int k0 = 0; k0 < N; k0 += BK) {
            float4 sv = *(const float4*)(Sb + k0 + sCol);
            Ss[sCol + 0][sRow] = sv.x; Ss[sCol + 1][sRow] = sv.y;
            Ss[sCol + 2][sRow] = sv.z; Ss[sCol + 3][sRow] = sv.w;

            float4 bv = *(const float4*)(Bb + (size_t)(k0 + bRow) * N + bCol);
            Bs[bRow][bCol + 0] = bv.x; Bs[bRow][bCol + 1] = bv.y;
            Bs[bRow][bCol + 2] = bv.z; Bs[bRow][bCol + 3] = bv.w;
            __syncthreads();

            #pragma unroll
            for (int k = 0; k < BK; k++) {
                float aF[TM], bF[TN];
                #pragma unroll
                for (int i = 0; i < TM; i++) aF[i] = Ss[k][tRow + i];
                #pragma unroll
                for (int j = 0; j < TN; j++) bF[j] = Bs[k][tCol + j];
                #pragma unroll
                for (int i = 0; i < TM; i++)
                    #pragma unroll
                    for (int j = 0; j < TN; j++) acc[i][j] += aF[i] * bF[j];
            }
            __syncthreads();
        }
    }

    // epilogue
    const int b0 = bm * BM + tRow;
    const int n0 = bn * BN + tCol;
    #pragma unroll
    for (int i = 0; i < TM; i++) {
        const int b = b0 + i;
        const size_t rowNow = ((size_t)b * T_ + t) * N;
        #pragma unroll
        for (int j = 0; j < TN; j++) {
            const int n = n0 + j;
            float u = g_U[rowNow + n];
            float sp_prev, mem_prev;
            if (t == 0) {
                sp_prev = 0.f;
                mem_prev = mem_init[(size_t)b * N + n];
            } else {
                const size_t rowPrev = rowNow - N;
                sp_prev = out_spikes[rowPrev + n];
                mem_prev = out_mems[rowPrev + n];
            }
            float y = tanhf(0.5f * acc[i][j] + u);
            float mem = mem_prev * 0.5f - 0.5f * (1.0f - sp_prev) + y;
            float sp = (mem > 0.5f) ? 1.0f : 0.0f;
            out_mems[rowNow + n] = mem;
            out_spikes[rowNow + n] = sp;
        }
    }
}

// ----------------------------------------------------------------------------
extern "C" void kernel_launch(void* const* d_in, const int* in_sizes, int n_in,
                              void* d_out, int out_size)
{
    const float* x        = (const float*)d_in[0];   // [256,128,700]
    const float* W_in     = (const float*)d_in[1];   // [700,2048]
    const float* Arec     = (const float*)d_in[2];   // [2048,2048]
    const float* bias     = (const float*)d_in[3];   // [2048]
    const float* mem_init = (const float*)d_in[4];   // [256,2048]

    float* out        = (float*)d_out;
    float* out_mems   = out;                                  // [256,128,2048]
    float* out_spikes = out + (size_t)B_ * T_ * H_;           // [256,128,2048]

    // 1) Precompute U' = 0.5*(x@W_in + bias) for all frames.
    {
        dim3 grid(H_ / 128, (B_ * T_) / 128);
        k_input_gemm<<<grid, 256>>>(x, W_in, bias);
    }

    // 2) Sequential recurrent frames (stream-ordered dependency chain).
    {
        dim3 grid(H_ / 64, B_ / 64);
        for (int t = 0; t < T_; t++)
            k_frame<<<grid, 256>>>(Arec, mem_init, out_mems, out_spikes, t);
    }
}

// round 2
// speedup vs baseline: 1.0000x; 1.0000x over previous
#include <cuda_runtime.h>
#include <math.h>

// Problem dims
#define B_    256
#define T_    128
#define NIN   700
#define H_    2048

// Scratch: U' = 0.5*(x@W_in + bias), layout [B*T, H]
__device__ float g_U[(size_t)B_ * T_ * H_];

// ----------------------------------------------------------------------------
// Kernel 1: input GEMM  C[M=B*T, N=H] = X[M, K=700] @ W[K, N], epilogue folds
// 0.5*(.+bias). Classic 128x128x8 SGEMM, 256 threads, 8x8 per thread.
// ----------------------------------------------------------------------------
__global__ void __launch_bounds__(256) k_input_gemm(
    const float* __restrict__ X, const float* __restrict__ W,
    const float* __restrict__ bias)
{
    constexpr int K = NIN, N = H_;
    constexpr int BM = 128, BN = 128, BK = 8, TM = 8, TN = 8;
    __shared__ float As[BK][BM];
    __shared__ float Bs[BK][BN];

    const int tid = threadIdx.x;
    const int bm = blockIdx.y, bn = blockIdx.x;

    const int aRow = tid >> 1;            // 0..127
    const int aCol = (tid & 1) << 2;      // 0 or 4
    const int bRow = tid >> 5;            // 0..7
    const int bCol = (tid & 31) << 2;     // 0..124

    const int tRow = (tid >> 4) << 3;     // 0..120
    const int tCol = (tid & 15) << 3;     // 0..120

    const float* Ab = X + (size_t)(bm * BM) * K;
    const float* Bb = W + bn * BN;

    float acc[TM][TN];
    #pragma unroll
    for (int i = 0; i < TM; i++)
        #pragma unroll
        for (int j = 0; j < TN; j++) acc[i][j] = 0.f;

    for (int k0 = 0; k0 < K; k0 += BK) {
        // load A tile (transposed into smem), guard ragged K=700
        #pragma unroll
        for (int i = 0; i < 4; i++) {
            int kk = k0 + aCol + i;
            As[aCol + i][aRow] = (kk < K) ? Ab[(size_t)aRow * K + kk] : 0.f;
        }
        // load B tile
        if (k0 + bRow < K) {
            float4 v = *(const float4*)(Bb + (size_t)(k0 + bRow) * N + bCol);
            Bs[bRow][bCol + 0] = v.x; Bs[bRow][bCol + 1] = v.y;
            Bs[bRow][bCol + 2] = v.z; Bs[bRow][bCol + 3] = v.w;
        } else {
            Bs[bRow][bCol + 0] = 0.f; Bs[bRow][bCol + 1] = 0.f;
            Bs[bRow][bCol + 2] = 0.f; Bs[bRow][bCol + 3] = 0.f;
        }
        __syncthreads();

        #pragma unroll
        for (int k = 0; k < BK; k++) {
            float aF[TM], bF[TN];
            #pragma unroll
            for (int i = 0; i < TM; i++) aF[i] = As[k][tRow + i];
            #pragma unroll
            for (int j = 0; j < TN; j++) bF[j] = Bs[k][tCol + j];
            #pragma unroll
            for (int i = 0; i < TM; i++)
                #pragma unroll
                for (int j = 0; j < TN; j++) acc[i][j] += aF[i] * bF[j];
        }
        __syncthreads();
    }

    const int m0 = bm * BM + tRow;
    const int n0 = bn * BN + tCol;
    #pragma unroll
    for (int i = 0; i < TM; i++) {
        size_t row = (size_t)(m0 + i) * N;
        #pragma unroll
        for (int j = 0; j < TN; j++)
            g_U[row + n0 + j] = 0.5f * (acc[i][j] + bias[n0 + j]);
    }
}

// ----------------------------------------------------------------------------
// Kernel 2: one recurrent frame.
//   r = spike_{t-1} @ A   (M=256 batch, K=H, N=H), fused epilogue:
//   y = tanh(0.5*r + U'), mem = mem_prev*0.5 - 0.5*(1-spike_prev) + y,
//   spike = mem > 0.5.
// Previous frame's mem/spike are read straight out of d_out (frame t-1 rows).
// 64x64x16 tile, 256 threads, 4x4 per thread. Grid 32x4 = 128 CTAs.
// ----------------------------------------------------------------------------
__global__ void __launch_bounds__(256) k_frame(
    const float* __restrict__ Arec, const float* __restrict__ mem_init,
    float* __restrict__ out_mems, float* __restrict__ out_spikes, int t)
{
    constexpr int N = H_;
    constexpr int BM = 64, BN = 64, BK = 16, TM = 4, TN = 4;
    __shared__ float Ss[BK][BM];
    __shared__ float Bs[BK][BN];

    const int tid = threadIdx.x;
    const int bm = blockIdx.y, bn = blockIdx.x;

    const int sRow = tid >> 2;            // 0..63 (batch within tile)
    const int sCol = (tid & 3) << 2;      // 0,4,8,12
    const int bRow = tid >> 4;            // 0..15
    const int bCol = (tid & 15) << 2;     // 0..60

    const int tRow = (tid >> 4) << 2;
    const int tCol = (tid & 15) << 2;

    float acc[TM][TN];
    #pragma unroll
    for (int i = 0; i < TM; i++)
        #pragma unroll
        for (int j = 0; j < TN; j++) acc[i][j] = 0.f;

    if (t > 0) {
        // spike rows for frame t-1: out_spikes[(b*T + t-1)*H + k]
        const size_t bstride = (size_t)T_ * N;
        const float* Sb = out_spikes + (size_t)(t - 1) * N
                        + (size_t)(bm * BM + sRow) * bstride;
        const float* Bb = Arec + bn * BN;

        for (int k0 = 0; k0 < N; k0 += BK) {
            float4 sv = *(const float4*)(Sb + k0 + sCol);
            Ss[sCol + 0][sRow] = sv.x; Ss[sCol + 1][sRow] = sv.y;
            Ss[sCol + 2][sRow] = sv.z; Ss[sCol + 3][sRow] = sv.w;

            float4 bv = *(const float4*)(Bb + (size_t)(k0 + bRow) * N + bCol);
            Bs[bRow][bCol + 0] = bv.x; Bs[bRow][bCol + 1] = bv.y;
            Bs[bRow][bCol + 2] = bv.z; Bs[bRow][bCol + 3] = bv.w;
            __syncthreads();

            #pragma unroll
            for (int k = 0; k < BK; k++) {
                float aF[TM], bF[TN];
                #pragma unroll
                for (int i = 0; i < TM; i++) aF[i] = Ss[k][tRow + i];
                #pragma unroll
                for (int j = 0; j < TN; j++) bF[j] = Bs[k][tCol + j];
                #pragma unroll
                for (int i = 0; i < TM; i++)
                    #pragma unroll
                    for (int j = 0; j < TN; j++) acc[i][j] += aF[i] * bF[j];
            }
            __syncthreads();
        }
    }

    // epilogue
    const int b0 = bm * BM + tRow;
    const int n0 = bn * BN + tCol;
    #pragma unroll
    for (int i = 0; i < TM; i++) {
        const int b = b0 + i;
        const size_t rowNow = ((size_t)b * T_ + t) * N;
        #pragma unroll
        for (int j = 0; j < TN; j++) {
            const int n = n0 + j;
            float u = g_U[rowNow + n];
            float sp_prev, mem_prev;
            if (t == 0) {
                sp_prev = 0.f;
                mem_prev = mem_init[(size_t)b * N + n];
            } else {
                const size_t rowPrev = rowNow - N;
                sp_prev = out_spikes[rowPrev + n];
                mem_prev = out_mems[rowPrev + n];
            }
            float y = tanhf(0.5f * acc[i][j] + u);
            float mem = mem_prev * 0.5f - 0.5f * (1.0f - sp_prev) + y;
            float sp = (mem > 0.5f) ? 1.0f : 0.0f;
            out_mems[rowNow + n] = mem;
            out_spikes[rowNow + n] = sp;
        }
    }
}

// ----------------------------------------------------------------------------
extern "C" void kernel_launch(void* const* d_in, const int* in_sizes, int n_in,
                              void* d_out, int out_size)
{
    const float* x        = (const float*)d_in[0];   // [256,128,700]
    const float* W_in     = (const float*)d_in[1];   // [700,2048]
    const float* Arec     = (const float*)d_in[2];   // [2048,2048]
    const float* bias     = (const float*)d_in[3];   // [2048]
    const float* mem_init = (const float*)d_in[4];   // [256,2048]

    float* out        = (float*)d_out;
    float* out_mems   = out;                                  // [256,128,2048]
    float* out_spikes = out + (size_t)B_ * T_ * H_;           // [256,128,2048]

    // 1) Precompute U' = 0.5*(x@W_in + bias) for all frames.
    {
        dim3 grid(H_ / 128, (B_ * T_) / 128);
        k_input_gemm<<<grid, 256>>>(x, W_in, bias);
    }

    // 2) Sequential recurrent frames (stream-ordered dependency chain).
    {
        dim3 grid(H_ / 64, B_ / 64);
        for (int t = 0; t < T_; t++)
            k_frame<<<grid, 256>>>(Arec, mem_init, out_mems, out_spikes, t);
    }
}

// round 6
// speedup vs baseline: 2.0496x; 2.0495x over previous
#include <cuda_runtime.h>
#include <cuda_bf16.h>
#include <math.h>
#include <stdint.h>

#define B_    256
#define T_    128
#define NIN   700
#define H_    2048

// ---------------- device scratch ----------------
__device__ float         g_U [(size_t)B_ * T_ * H_];    // 0.5*(x@W+bias)
__device__ __nv_bfloat16 gA0 [(size_t)H_ * H_];         // A^T splits [n][k]
__device__ __nv_bfloat16 gA1 [(size_t)H_ * H_];
__device__ __nv_bfloat16 gA2 [(size_t)H_ * H_];
__device__ __nv_bfloat16 gS  [2][(size_t)B_ * H_];      // spike ping-pong (exact 0/1)

// ---------------- asm helpers (sm_80+ portable) ----------------
__device__ __forceinline__ uint32_t smem_u32(const void* p) {
    uint32_t a;
    asm("{ .reg .u64 t; cvta.to.shared.u64 t, %1; cvt.u32.u64 %0, t; }"
        : "=r"(a) : "l"(p));
    return a;
}
__device__ __forceinline__ void cpa16(uint32_t dst, const void* src) {
    asm volatile("cp.async.cg.shared.global [%0], [%1], 16;"
                 :: "r"(dst), "l"(src) : "memory");
}
#define CP_COMMIT() asm volatile("cp.async.commit_group;" ::: "memory")
#define CP_WAIT1()  asm volatile("cp.async.wait_group 1;" ::: "memory")
#define CP_WAIT0()  asm volatile("cp.async.wait_group 0;" ::: "memory")

__device__ __forceinline__ void ldsm4(uint32_t* r, uint32_t a) {
    asm volatile("ldmatrix.sync.aligned.m8n8.x4.shared.b16 {%0,%1,%2,%3}, [%4];"
                 : "=r"(r[0]), "=r"(r[1]), "=r"(r[2]), "=r"(r[3]) : "r"(a));
}
__device__ __forceinline__ void ldsm2(uint32_t* r, uint32_t a) {
    asm volatile("ldmatrix.sync.aligned.m8n8.x2.shared.b16 {%0,%1}, [%2];"
                 : "=r"(r[0]), "=r"(r[1]) : "r"(a));
}
__device__ __forceinline__ void mma16816(float* c, const uint32_t* a,
                                         const uint32_t* b) {
    asm volatile("mma.sync.aligned.m16n8k16.row.col.f32.bf16.bf16.f32 "
                 "{%0,%1,%2,%3}, {%4,%5,%6,%7}, {%8,%9}, {%0,%1,%2,%3};"
                 : "+f"(c[0]), "+f"(c[1]), "+f"(c[2]), "+f"(c[3])
                 : "r"(a[0]), "r"(a[1]), "r"(a[2]), "r"(a[3]),
                   "r"(b[0]), "r"(b[1]));
}

// ---------------- bf16 3-way exact split ----------------
__device__ __forceinline__ void split3(float v, __nv_bfloat16& b0,
                                       __nv_bfloat16& b1, __nv_bfloat16& b2) {
    b0 = __float2bfloat16(v);
    float f0 = __bfloat162float(b0);
    b1 = __float2bfloat16(v - f0);
    float f1 = __bfloat162float(b1);
    b2 = __float2bfloat16(v - f0 - f1);
}

__global__ void k_split_A(const float* __restrict__ A) {
    __shared__ float tile[32][33];
    int tx = threadIdx.x, ty = threadIdx.y;
    int kbase = blockIdx.y * 32, nbase = blockIdx.x * 32;
    #pragma unroll
    for (int i = 0; i < 32; i += 8)
        tile[ty + i][tx] = A[(size_t)(kbase + ty + i) * H_ + nbase + tx];
    __syncthreads();
    #pragma unroll
    for (int i = 0; i < 32; i += 8) {
        float v = tile[tx][ty + i];
        size_t o = (size_t)(nbase + ty + i) * H_ + kbase + tx;
        __nv_bfloat16 b0, b1, b2; split3(v, b0, b1, b2);
        gA0[o] = b0; gA1[o] = b1; gA2[o] = b2;
    }
}

// ---------------- input GEMM (fp32 SIMT — bit-identical to round 1) --------
__global__ void __launch_bounds__(256) k_input_gemm(
    const float* __restrict__ X, const float* __restrict__ W,
    const float* __restrict__ bias)
{
    constexpr int K = NIN, N = H_;
    constexpr int BM = 128, BN = 128, BK = 8, TM = 8, TN = 8;
    __shared__ float As[BK][BM];
    __shared__ float Bs[BK][BN];

    const int tid = threadIdx.x;
    const int bm = blockIdx.y, bn = blockIdx.x;
    const int aRow = tid >> 1, aCol = (tid & 1) << 2;
    const int bRow = tid >> 5, bCol = (tid & 31) << 2;
    const int tRow = (tid >> 4) << 3, tCol = (tid & 15) << 3;

    const float* Ab = X + (size_t)(bm * BM) * K;
    const float* Bb = W + bn * BN;

    float acc[TM][TN];
    #pragma unroll
    for (int i = 0; i < TM; i++)
        #pragma unroll
        for (int j = 0; j < TN; j++) acc[i][j] = 0.f;

    for (int k0 = 0; k0 < K; k0 += BK) {
        #pragma unroll
        for (int i = 0; i < 4; i++) {
            int kk = k0 + aCol + i;
            As[aCol + i][aRow] = (kk < K) ? Ab[(size_t)aRow * K + kk] : 0.f;
        }
        if (k0 + bRow < K) {
            float4 v = *(const float4*)(Bb + (size_t)(k0 + bRow) * N + bCol);
            Bs[bRow][bCol + 0] = v.x; Bs[bRow][bCol + 1] = v.y;
            Bs[bRow][bCol + 2] = v.z; Bs[bRow][bCol + 3] = v.w;
        } else {
            Bs[bRow][bCol + 0] = 0.f; Bs[bRow][bCol + 1] = 0.f;
            Bs[bRow][bCol + 2] = 0.f; Bs[bRow][bCol + 3] = 0.f;
        }
        __syncthreads();
        #pragma unroll
        for (int k = 0; k < BK; k++) {
            float aF[TM], bF[TN];
            #pragma unroll
            for (int i = 0; i < TM; i++) aF[i] = As[k][tRow + i];
            #pragma unroll
            for (int j = 0; j < TN; j++) bF[j] = Bs[k][tCol + j];
            #pragma unroll
            for (int i = 0; i < TM; i++)
                #pragma unroll
                for (int j = 0; j < TN; j++) acc[i][j] += aF[i] * bF[j];
        }
        __syncthreads();
    }
    const int m0 = bm * BM + tRow, n0 = bn * BN + tCol;
    #pragma unroll
    for (int i = 0; i < TM; i++) {
        size_t row = (size_t)(m0 + i) * N;
        #pragma unroll
        for (int j = 0; j < TN; j++)
            g_U[row + n0 + j] = 0.5f * (acc[i][j] + bias[n0 + j]);
    }
}

// ---------------- frame 0 (spike0 = 0 -> r = 0) ----------------
__global__ void k_frame0(const float* __restrict__ mem_init,
                         float* __restrict__ out_mems,
                         float* __restrict__ out_spikes)
{
    size_t idx = (size_t)blockIdx.x * 256 + threadIdx.x;
    int b = (int)(idx / H_), n = (int)(idx % H_);
    size_t o = ((size_t)b * T_) * H_ + n;
    float u = g_U[o];
    float y = tanhf(u);
    float mem = mem_init[idx] * 0.5f - 0.5f * (1.0f - 0.0f) + y;
    float sp = (mem > 0.5f) ? 1.0f : 0.0f;
    out_mems[o] = mem;
    out_spikes[o] = sp;
    gS[0][idx] = __float2bfloat16(sp);
}

// ---- recurrent frame t >= 1: 3-term exact bf16 mma, CHUNKED accumulation --
// Per K-stage (BK=32, 6 mma chained) the tensor-core accumulator starts from
// ZERO (tacc) and is folded into the master accumulator with an IEEE fp32 add.
// This bounds HMMA-internal truncation to fresh small partials and restores
// the fp32-class (~1e-7) noise level of the known-passing round-1 kernel.
#define SPD 40                           // padded row stride (bf16 elems)
#define FTILE (64 * SPD)

__global__ void __launch_bounds__(256)
k_frame_mma(float* __restrict__ out_mems, float* __restrict__ out_spikes, int t)
{
    __shared__ __align__(16) __nv_bfloat16 smf[2][4][FTILE];   // 40960 B
    const int tid = threadIdx.x;
    const int lane = tid & 31, w = tid >> 5;
    const int wm = w & 1, wn = w >> 1;            // warp tile 32(m) x 16(n)
    const int l15 = lane & 15;
    const int n0 = blockIdx.x * 64, m0 = blockIdx.y * 64;

    const __nv_bfloat16* Sg = gS[(t + 1) & 1];
    const __nv_bfloat16* Ap[3] = { gA0 + (size_t)n0 * H_,
                                   gA1 + (size_t)n0 * H_,
                                   gA2 + (size_t)n0 * H_ };

    const int lr = tid >> 2, lj = (tid & 3) * 8;
    auto load_stage = [&](int buf, int k0) {
        cpa16(smem_u32(&smf[buf][0][lr * SPD + lj]),
              Sg + (size_t)(m0 + lr) * H_ + k0 + lj);
        #pragma unroll
        for (int p = 0; p < 3; p++)
            cpa16(smem_u32(&smf[buf][1 + p][lr * SPD + lj]),
                  Ap[p] + (size_t)lr * H_ + k0 + lj);
    };

    float master[2][2][4];
    #pragma unroll
    for (int a = 0; a < 2; a++)
        #pragma unroll
        for (int b = 0; b < 2; b++)
            #pragma unroll
            for (int c = 0; c < 4; c++) master[a][b][c] = 0.f;

    load_stage(0, 0); CP_COMMIT();

    constexpr int NS = H_ / 32;     // 64 stages, BK=32
    for (int s = 0; s < NS; s++) {
        int buf = s & 1;
        if (s + 1 < NS) { load_stage(buf ^ 1, (s + 1) * 32); CP_COMMIT(); CP_WAIT1(); }
        else CP_WAIT0();
        __syncthreads();

        // fresh tensor-core accumulator per stage
        float tacc[2][2][4];
        #pragma unroll
        for (int a = 0; a < 2; a++)
            #pragma unroll
            for (int b = 0; b < 2; b++)
                #pragma unroll
                for (int c = 0; c < 4; c++) tacc[a][b][c] = 0.f;

        uint32_t sb = smem_u32(&smf[buf][0][0]);
        #pragma unroll
        for (int kk = 0; kk < 2; kk++) {
            uint32_t af[2][4];
            #pragma unroll
            for (int mi = 0; mi < 2; mi++) {
                int row = wm * 32 + mi * 16 + l15;
                ldsm4(af[mi], sb + (uint32_t)((row * SPD + (lane >> 4) * 8) * 2 + kk * 32));
            }
            #pragma unroll
            for (int p = 0; p < 3; p++) {
                uint32_t ab = smem_u32(&smf[buf][1 + p][0]);
                #pragma unroll
                for (int ni = 0; ni < 2; ni++) {
                    uint32_t bf[2];
                    int row = wn * 16 + ni * 8 + (l15 & 7);
                    ldsm2(bf, ab + (uint32_t)((row * SPD + ((l15 >> 3) & 1) * 8) * 2 + kk * 32));
                    mma16816(tacc[0][ni], af[0], bf);
                    mma16816(tacc[1][ni], af[1], bf);
                }
            }
        }

        // IEEE fp32 fold into master
        #pragma unroll
        for (int a = 0; a < 2; a++)
            #pragma unroll
            for (int b = 0; b < 2; b++)
                #pragma unroll
                for (int c = 0; c < 4; c++) master[a][b][c] += tacc[a][b][c];

        __syncthreads();
    }

    // fused epilogue — arithmetic identical to the passing round-1 kernel
    __nv_bfloat16* Sout = gS[t & 1];
    const int gq = lane >> 2, tq = lane & 3;
    #pragma unroll
    for (int mi = 0; mi < 2; mi++)
        #pragma unroll
        for (int ni = 0; ni < 2; ni++)
            #pragma unroll
            for (int h = 0; h < 2; h++)
                #pragma unroll
                for (int e = 0; e < 2; e++) {
                    int b = m0 + wm * 32 + mi * 16 + gq + h * 8;
                    int n = n0 + wn * 16 + ni * 8 + tq * 2 + e;
                    size_t o = ((size_t)b * T_ + t) * H_ + n;
                    float u = g_U[o];
                    float sp_prev  = out_spikes[o - H_];
                    float mem_prev = out_mems[o - H_];
                    float y = tanhf(0.5f * master[mi][ni][h * 2 + e] + u);
                    float mem = mem_prev * 0.5f - 0.5f * (1.0f - sp_prev) + y;
                    float sp = (mem > 0.5f) ? 1.0f : 0.0f;
                    out_mems[o] = mem;
                    out_spikes[o] = sp;
                    Sout[(size_t)b * H_ + n] = __float2bfloat16(sp);
                }
}

// ----------------------------------------------------------------------------
extern "C" void kernel_launch(void* const* d_in, const int* in_sizes, int n_in,
                              void* d_out, int out_size)
{
    const float* x        = (const float*)d_in[0];
    const float* W_in     = (const float*)d_in[1];
    const float* Arec     = (const float*)d_in[2];
    const float* bias     = (const float*)d_in[3];
    const float* mem_init = (const float*)d_in[4];

    float* out        = (float*)d_out;
    float* out_mems   = out;
    float* out_spikes = out + (size_t)B_ * T_ * H_;

    { dim3 g(H_ / 32, H_ / 32), b(32, 8); k_split_A<<<g, b>>>(Arec); }
    { dim3 g(H_ / 128, (B_ * T_) / 128); k_input_gemm<<<g, 256>>>(x, W_in, bias); }

    k_frame0<<<(B_ * H_) / 256, 256>>>(mem_init, out_mems, out_spikes);

    dim3 g(H_ / 64, B_ / 64);
    for (int t = 1; t < T_; t++)
        k_frame_mma<<<g, 256>>>(out_mems, out_spikes, t);
}